// round 1
// baseline (speedup 1.0000x reference)
#include <cuda_runtime.h>
#include <math.h>

#define L_ 520
#define V_ 32128
#define R_ 512
#define KK 8            // K = L - R
#define NROWS 9         // rows R-1 .. L-1 need softmax stats
#define OUT_PROBS_OFF 521
#define OUT_NMATCH (521 + (size_t)L_ * V_)

struct Scratch {
    float rmax[NROWS];
    float rsuminv[NROWS];
    int   rargmax[NROWS];
    int   n_match;
};
__device__ Scratch g_s;

// ---------------------------------------------------------------------------
// Kernel 1: per-row max / argmax / sum-of-exp for the 9 rows we actually need.
// One block per row, 1024 threads, float4 loads (V_ % 4 == 0).
// ---------------------------------------------------------------------------
__global__ void rowstats_kernel(const float* __restrict__ logits) {
    const int i = blockIdx.x;                       // 0..8
    const float* row = logits + (size_t)(R_ - 1 + i) * V_;
    const int tid = threadIdx.x;
    const int nth = blockDim.x;

    __shared__ float s_val[1024];
    __shared__ int   s_idx[1024];

    // pass 1: max + first-index argmax
    float m = -INFINITY; int am = 0x7fffffff;
    for (int c = tid * 4; c < V_; c += nth * 4) {
        float4 v = *(const float4*)(row + c);
        if (v.x > m) { m = v.x; am = c; }
        if (v.y > m) { m = v.y; am = c + 1; }
        if (v.z > m) { m = v.z; am = c + 2; }
        if (v.w > m) { m = v.w; am = c + 3; }
    }
    s_val[tid] = m; s_idx[tid] = am;
    __syncthreads();
    for (int s = nth >> 1; s > 0; s >>= 1) {
        if (tid < s) {
            float mv = s_val[tid + s]; int mi = s_idx[tid + s];
            if (mv > s_val[tid] || (mv == s_val[tid] && mi < s_idx[tid])) {
                s_val[tid] = mv; s_idx[tid] = mi;
            }
        }
        __syncthreads();
    }
    const float rowmax = s_val[0];
    const int   rowarg = s_idx[0];
    __syncthreads();

    // pass 2: sum of exp (row is L2/L1-hot after pass 1)
    float acc = 0.f;
    for (int c = tid * 4; c < V_; c += nth * 4) {
        float4 v = *(const float4*)(row + c);
        acc += expf(v.x - rowmax) + expf(v.y - rowmax)
             + expf(v.z - rowmax) + expf(v.w - rowmax);
    }
    s_val[tid] = acc;
    __syncthreads();
    for (int s = nth >> 1; s > 0; s >>= 1) {
        if (tid < s) s_val[tid] += s_val[tid + s];
        __syncthreads();
    }
    if (tid == 0) {
        g_s.rmax[i]    = rowmax;
        g_s.rsuminv[i] = 1.0f / s_val[0];
        g_s.rargmax[i] = rowarg;
    }
}

// ---------------------------------------------------------------------------
// Kernel 2: accept chain + n_match + id outputs + n_match scalar output.
// Detects whether input_ids is int64 or int32 (JAX x64 ambiguity) by checking
// that all odd 32-bit words in the first L_ words are zero (int64 layout).
// ---------------------------------------------------------------------------
__global__ void decide_kernel(const void* __restrict__ ids_raw,
                              const float* __restrict__ logits,
                              const float* __restrict__ probs,
                              float* __restrict__ out) {
    __shared__ int s_flag;
    __shared__ int s_nm;
    const int tid = threadIdx.x;
    const int* w = (const int*)ids_raw;
    if (tid == 0) s_flag = 0;
    __syncthreads();
    for (int j = 1 + 2 * tid; j < L_; j += 2 * blockDim.x)
        if (w[j] != 0) atomicOr(&s_flag, 1);
    __syncthreads();
    const int is64 = (s_flag == 0);
    const long long* w64 = (const long long*)ids_raw;

    if (tid == 0) {
        int nm = 0; bool chain = true;
        for (int i = 0; i < KK; i++) {
            int d = is64 ? (int)w64[R_ + i] : w[R_ + i];
            float tp = expf(logits[(size_t)(R_ - 1 + i) * V_ + d] - g_s.rmax[i]) * g_s.rsuminv[i];
            float pp = probs [(size_t)(R_ - 1 + i) * V_ + d];
            // leniency = 2 (>1), so lenient term active: tp > pp/2
            bool acc = (g_s.rargmax[i] == d) || (tp > pp * 0.5f);
            if (chain && acc) nm++; else chain = false;
        }
        g_s.n_match = nm;
        s_nm = nm;
        out[OUT_NMATCH] = (float)nm;
    }
    __syncthreads();
    const int nm = s_nm;

    // id_res[0:512] = input_ids[0:512]
    for (int j = tid; j < R_; j += blockDim.x)
        out[j] = (float)(is64 ? (int)w64[j] : w[j]);

    // id_res[512:521] = new_ids (pos 0..K)
    if (tid <= KK) {
        int pos = tid, v;
        if      (pos < nm)  v = is64 ? (int)w64[R_ + pos] : w[R_ + pos];  // pos<=7 here
        else if (pos == nm) v = g_s.rargmax[pos];
        else                v = 0;
        out[R_ + pos] = (float)v;
    }
}

// ---------------------------------------------------------------------------
// Kernel 3: the big output write (520 x 32128 floats at offset 521).
// Rows < 512: copy of probs. Rows 512+i: softmax(logits row 511+i) if
// i < n_match else zeros. float4 loads; scalar stores (offset 521 => base is
// only 4B-aligned, STG.128 would trap).
// ---------------------------------------------------------------------------
__global__ void bigout_kernel(const float* __restrict__ probs,
                              const float* __restrict__ logits,
                              float* __restrict__ out) {
    const int row = blockIdx.y;
    const int c4  = blockIdx.x * blockDim.x + threadIdx.x;
    if (c4 >= V_ / 4) return;
    const int col = c4 * 4;
    float* o = out + OUT_PROBS_OFF + (size_t)row * V_ + col;
    if (row < R_) {
        float4 v = *(const float4*)(probs + (size_t)row * V_ + col);
        o[0] = v.x; o[1] = v.y; o[2] = v.z; o[3] = v.w;
    } else {
        const int i = row - R_;
        if (i < g_s.n_match) {
            const float m = g_s.rmax[i], si = g_s.rsuminv[i];
            float4 v = *(const float4*)(logits + (size_t)(R_ - 1 + i) * V_ + col);
            o[0] = expf(v.x - m) * si;
            o[1] = expf(v.y - m) * si;
            o[2] = expf(v.z - m) * si;
            o[3] = expf(v.w - m) * si;
        } else {
            o[0] = 0.f; o[1] = 0.f; o[2] = 0.f; o[3] = 0.f;
        }
    }
}

// ---------------------------------------------------------------------------
extern "C" void kernel_launch(void* const* d_in, const int* in_sizes, int n_in,
                              void* d_out, int out_size) {
    const float* logits = (const float*)d_in[0];   // target_logits (1,520,32128) f32
    const float* probs  = (const float*)d_in[1];   // probs         (1,520,32128) f32
    const void*  ids    = d_in[2];                 // input_ids (1,520) int64 or int32
    float* out = (float*)d_out;                    // [521 ids | 520*32128 probs | n_match]

    rowstats_kernel<<<NROWS, 1024>>>(logits);
    decide_kernel<<<1, 128>>>(ids, logits, probs, out);
    dim3 g3((V_ / 4 + 255) / 256, L_);
    bigout_kernel<<<g3, 256>>>(probs, logits, out);
}